// round 2
// baseline (speedup 1.0000x reference)
#include <cuda_runtime.h>
#include <cuda_bf16.h>
#include <stdint.h>

#define N_NODES 50000
#define N_EDGES 800000
#define IN_F    128
#define OUT_F   64

// Scratch (allocation-free rule: __device__ globals)
__device__ float g_h[(size_t)N_NODES * OUT_F];   // 12.8 MB, L2-resident
__device__ float g_Wt[IN_F * OUT_F];             // W transposed: Wt[k][o]

// ---------------------------------------------------------------------------
// Tiny transpose: Wt[k*64 + o] = W[o*128 + k]
// ---------------------------------------------------------------------------
__global__ void transpose_W_kernel(const float* __restrict__ W) {
    int idx = blockIdx.x * blockDim.x + threadIdx.x;
    if (idx < IN_F * OUT_F) {
        int o = idx >> 7;      // /128
        int k = idx & 127;
        g_Wt[k * OUT_F + o] = W[idx];
    }
}

// ---------------------------------------------------------------------------
// GEMM: h = feat @ W^T + b
// Tile: 32 nodes x 64 outs per block (256 threads).
// Thread = (nl, og): computes nodes {node0+nl, node0+nl+16} x outs {og*4..og*4+3}
// smem: Wt tile (conflict-free float4 reads), feat tile (broadcast reads).
// ---------------------------------------------------------------------------
__global__ __launch_bounds__(256) void gemm_kernel(
    const float* __restrict__ feat,
    const float* __restrict__ b)
{
    __shared__ float sW[IN_F * OUT_F];   // 32 KB, layout [k][o]
    __shared__ float sF[32 * IN_F];      // 16 KB, layout [n_local][k]

    const int tid = threadIdx.x;
    const int node0 = blockIdx.x * 32;

    // Load Wt (already [k][o], contiguous) — coalesced, conflict-free STS
    {
        const float4* src = (const float4*)g_Wt;
        float4* dst = (float4*)sW;
        #pragma unroll
        for (int i = 0; i < 8; i++) dst[tid + i * 256] = src[tid + i * 256];
    }
    // Load 32 feat rows (float4), zero-pad past N_NODES
    {
        const float4* src = (const float4*)feat;
        float4* dst = (float4*)sF;
        #pragma unroll
        for (int i = 0; i < 4; i++) {
            int idx = tid + i * 256;         // float4 index in tile
            int n   = idx >> 5;              // 32 float4 per row
            int node = node0 + n;
            dst[idx] = (node < N_NODES) ? src[(size_t)node * 32 + (idx & 31)]
                                        : make_float4(0.f, 0.f, 0.f, 0.f);
        }
    }
    __syncthreads();

    const int og = tid & 15;    // output group: outs og*4 .. og*4+3
    const int nl = tid >> 4;    // 0..15 -> nodes nl and nl+16

    const float4 bv = ((const float4*)b)[og];
    float a00 = bv.x, a01 = bv.y, a02 = bv.z, a03 = bv.w;
    float a10 = bv.x, a11 = bv.y, a12 = bv.z, a13 = bv.w;

    const float4* fA = (const float4*)(sF + nl * IN_F);
    const float4* fB = (const float4*)(sF + (nl + 16) * IN_F);

    #pragma unroll
    for (int k4 = 0; k4 < IN_F / 4; k4++) {
        float4 f0 = fA[k4];
        float4 f1 = fB[k4];
        #pragma unroll
        for (int j = 0; j < 4; j++) {
            const float4 w = *(const float4*)(sW + (k4 * 4 + j) * OUT_F + og * 4);
            const float fa = (&f0.x)[j];
            const float fb = (&f1.x)[j];
            a00 = fmaf(fa, w.x, a00); a01 = fmaf(fa, w.y, a01);
            a02 = fmaf(fa, w.z, a02); a03 = fmaf(fa, w.w, a03);
            a10 = fmaf(fb, w.x, a10); a11 = fmaf(fb, w.y, a11);
            a12 = fmaf(fb, w.z, a12); a13 = fmaf(fb, w.w, a13);
        }
    }

    const int nodeA = node0 + nl;
    const int nodeB = node0 + nl + 16;
    if (nodeA < N_NODES)
        *(float4*)(g_h + (size_t)nodeA * OUT_F + og * 4) = make_float4(a00, a01, a02, a03);
    if (nodeB < N_NODES)
        *(float4*)(g_h + (size_t)nodeB * OUT_F + og * 4) = make_float4(a10, a11, a12, a13);
}

// ---------------------------------------------------------------------------
// Scatter: out[dst] += h[src] * w, one warp per edge.
// Lane l owns floats [2l, 2l+1] of the 64-wide row.
// h gathers hit L2 (table is 12.8 MB); atomicAdd (no return) -> REDG.
// NOTE: edge indices are int32 (JAX x64 disabled downcasts int64 -> int32).
// ---------------------------------------------------------------------------
__global__ __launch_bounds__(256) void scatter_kernel(
    const int* __restrict__ esrc,
    const int* __restrict__ edst,
    const float* __restrict__ ew,
    float* __restrict__ out)
{
    const int warp_in_blk = threadIdx.x >> 5;
    const int lane = threadIdx.x & 31;
    const int e = blockIdx.x * 8 + warp_in_blk;   // 8 warps per block
    if (e >= N_EDGES) return;

    const int s = esrc[e];   // broadcast within warp
    const int d = edst[e];
    const float w = ew[e];

    const float2 hv = *(const float2*)(g_h + (size_t)s * OUT_F + lane * 2);
    float* o = out + (size_t)d * OUT_F + lane * 2;
    atomicAdd(o,     hv.x * w);
    atomicAdd(o + 1, hv.y * w);
}

// ---------------------------------------------------------------------------
extern "C" void kernel_launch(void* const* d_in, const int* in_sizes, int n_in,
                              void* d_out, int out_size) {
    const float* feat = (const float*)d_in[0];
    const int*   esrc = (const int*)d_in[1];
    const int*   edst = (const int*)d_in[2];
    const float* ew   = (const float*)d_in[3];
    const float* W    = (const float*)d_in[4];
    const float* b    = (const float*)d_in[5];
    float* out = (float*)d_out;

    // Zero the output: segments with no incoming edges must be exactly 0.
    cudaMemsetAsync(out, 0, (size_t)N_NODES * OUT_F * sizeof(float));

    transpose_W_kernel<<<(IN_F * OUT_F + 255) / 256, 256>>>(W);

    gemm_kernel<<<(N_NODES + 31) / 32, 256>>>(feat, b);

    // one warp per edge: 800000 edges / 8 warps-per-block = 100000 blocks
    scatter_kernel<<<N_EDGES / 8, 256>>>(esrc, edst, ew, out);
}

// round 3
// speedup vs baseline: 1.3428x; 1.3428x over previous
#include <cuda_runtime.h>
#include <cuda_bf16.h>
#include <stdint.h>

#define N_NODES 50000
#define N_EDGES 800000
#define IN_F    128
#define OUT_F   64

// Scratch (allocation-free rule: __device__ globals)
__device__ float g_h[(size_t)N_NODES * OUT_F];   // 12.8 MB, L2-resident
__device__ float g_Wt[IN_F * OUT_F];             // W transposed: Wt[k][o]

// ---------------------------------------------------------------------------
// Prep: zero the output (segments with no edges must be exactly 0) AND
// transpose W into g_Wt. One launch instead of memset + transpose.
// ---------------------------------------------------------------------------
__global__ __launch_bounds__(256) void prep_kernel(const float* __restrict__ W,
                                                   float4* __restrict__ out4) {
    const int idx = blockIdx.x * 256 + threadIdx.x;
    if (idx < IN_F * OUT_F) {          // 8192 threads transpose W
        int o = idx >> 7;              // /128
        int k = idx & 127;
        g_Wt[k * OUT_F + o] = W[idx];
    }
    if (idx < (N_NODES * OUT_F) / 4)   // 800000 float4 stores zero out
        out4[idx] = make_float4(0.f, 0.f, 0.f, 0.f);
}

// ---------------------------------------------------------------------------
// GEMM: h = feat @ W^T + b
// Tile: 32 nodes x 64 outs per block (256 threads).
// Thread = (nl, og): computes nodes {node0+nl, node0+nl+16} x outs {og*4..og*4+3}
// ---------------------------------------------------------------------------
__global__ __launch_bounds__(256) void gemm_kernel(
    const float* __restrict__ feat,
    const float* __restrict__ b)
{
    __shared__ float sW[IN_F * OUT_F];   // 32 KB, layout [k][o]
    __shared__ float sF[32 * IN_F];      // 16 KB, layout [n_local][k]

    const int tid = threadIdx.x;
    const int node0 = blockIdx.x * 32;

    // Load Wt (already [k][o], contiguous) — coalesced, conflict-free STS
    {
        const float4* src = (const float4*)g_Wt;
        float4* dst = (float4*)sW;
        #pragma unroll
        for (int i = 0; i < 8; i++) dst[tid + i * 256] = src[tid + i * 256];
    }
    // Load 32 feat rows (float4), zero-pad past N_NODES
    {
        const float4* src = (const float4*)feat;
        float4* dst = (float4*)sF;
        #pragma unroll
        for (int i = 0; i < 4; i++) {
            int idx = tid + i * 256;         // float4 index in tile
            int n   = idx >> 5;              // 32 float4 per row
            int node = node0 + n;
            dst[idx] = (node < N_NODES) ? src[(size_t)node * 32 + (idx & 31)]
                                        : make_float4(0.f, 0.f, 0.f, 0.f);
        }
    }
    __syncthreads();

    const int og = tid & 15;    // output group: outs og*4 .. og*4+3
    const int nl = tid >> 4;    // 0..15 -> nodes nl and nl+16

    const float4 bv = ((const float4*)b)[og];
    float a00 = bv.x, a01 = bv.y, a02 = bv.z, a03 = bv.w;
    float a10 = bv.x, a11 = bv.y, a12 = bv.z, a13 = bv.w;

    const float4* fA = (const float4*)(sF + nl * IN_F);
    const float4* fB = (const float4*)(sF + (nl + 16) * IN_F);

    #pragma unroll
    for (int k4 = 0; k4 < IN_F / 4; k4++) {
        float4 f0 = fA[k4];
        float4 f1 = fB[k4];
        #pragma unroll
        for (int j = 0; j < 4; j++) {
            const float4 w = *(const float4*)(sW + (k4 * 4 + j) * OUT_F + og * 4);
            const float fa = (&f0.x)[j];
            const float fb = (&f1.x)[j];
            a00 = fmaf(fa, w.x, a00); a01 = fmaf(fa, w.y, a01);
            a02 = fmaf(fa, w.z, a02); a03 = fmaf(fa, w.w, a03);
            a10 = fmaf(fb, w.x, a10); a11 = fmaf(fb, w.y, a11);
            a12 = fmaf(fb, w.z, a12); a13 = fmaf(fb, w.w, a13);
        }
    }

    const int nodeA = node0 + nl;
    const int nodeB = node0 + nl + 16;
    if (nodeA < N_NODES)
        *(float4*)(g_h + (size_t)nodeA * OUT_F + og * 4) = make_float4(a00, a01, a02, a03);
    if (nodeB < N_NODES)
        *(float4*)(g_h + (size_t)nodeB * OUT_F + og * 4) = make_float4(a10, a11, a12, a13);
}

// ---------------------------------------------------------------------------
// Scatter: out[dst] += h[src] * w.
// One edge per HALF-warp: lane16 owns float4 chunk lane16*4 of the 64-wide row.
// Vector reduction red.global.add.v4.f32 (PTX 8.1+, sm_90+): 16 REDG ops/edge
// instead of 64 scalar ones -> 4x fewer LTS atomic-ALU ops.
// ---------------------------------------------------------------------------
__device__ __forceinline__ void red_add_v4(float* ptr, float4 v) {
    asm volatile("red.global.add.v4.f32 [%0], {%1, %2, %3, %4};"
                 :: "l"(ptr), "f"(v.x), "f"(v.y), "f"(v.z), "f"(v.w)
                 : "memory");
}

__global__ __launch_bounds__(256) void scatter_kernel(
    const int* __restrict__ esrc,
    const int* __restrict__ edst,
    const float* __restrict__ ew,
    float* __restrict__ out)
{
    const int half_id = threadIdx.x >> 4;         // 0..15 within block
    const int lane16  = threadIdx.x & 15;
    const int e = blockIdx.x * 16 + half_id;      // 16 edges per block
    if (e >= N_EDGES) return;

    const int   s = esrc[e];    // broadcast within half-warp
    const int   d = edst[e];
    const float w = ew[e];

    float4 hv = *(const float4*)(g_h + (size_t)s * OUT_F + lane16 * 4);
    hv.x *= w; hv.y *= w; hv.z *= w; hv.w *= w;
    red_add_v4(out + (size_t)d * OUT_F + lane16 * 4, hv);
}

// ---------------------------------------------------------------------------
extern "C" void kernel_launch(void* const* d_in, const int* in_sizes, int n_in,
                              void* d_out, int out_size) {
    const float* feat = (const float*)d_in[0];
    const int*   esrc = (const int*)d_in[1];   // int32 (JAX x64 disabled)
    const int*   edst = (const int*)d_in[2];
    const float* ew   = (const float*)d_in[3];
    const float* W    = (const float*)d_in[4];
    const float* b    = (const float*)d_in[5];
    float* out = (float*)d_out;

    // Zero out + transpose W in one launch (800000 float4 zero-stores)
    prep_kernel<<<(N_NODES * OUT_F / 4 + 255) / 256, 256>>>(W, (float4*)out);

    gemm_kernel<<<(N_NODES + 31) / 32, 256>>>(feat, b);

    // 16 edges per block (one per half-warp): 800000/16 = 50000 blocks
    scatter_kernel<<<N_EDGES / 16, 256>>>(esrc, edst, ew, out);
}

// round 4
// speedup vs baseline: 1.5142x; 1.1276x over previous
#include <cuda_runtime.h>
#include <cuda_bf16.h>
#include <stdint.h>

#define N_NODES 50000
#define N_EDGES 800000
#define IN_F    128
#define OUT_F   64

// Scratch (allocation-free rule: __device__ globals)
__device__ float g_h[(size_t)N_NODES * OUT_F];   // 12.8 MB, L2-resident
__device__ float g_Wt[IN_F * OUT_F];             // W transposed: Wt[k][o]

// ---------------------------------------------------------------------------
// Prep: transpose W only (tiny). Output zeroing moved into gemm_kernel.
// ---------------------------------------------------------------------------
__global__ __launch_bounds__(256) void prep_kernel(const float* __restrict__ W) {
    const int idx = blockIdx.x * 256 + threadIdx.x;
    if (idx < IN_F * OUT_F) {
        int o = idx >> 7;      // /128
        int k = idx & 127;
        g_Wt[k * OUT_F + o] = W[idx];
    }
}

// ---------------------------------------------------------------------------
// GEMM: h = feat @ W^T + b
// Tile: 64 nodes x 64 outs per block (256 threads), 4 nodes x 4 outs/thread.
// LDS traffic: 2 B/FMA -> balanced with the FFMA issue floor (~43k cyc chip).
// Also zeroes `out` (4 float4 stores/thread, hidden behind compute).
// ---------------------------------------------------------------------------
__global__ __launch_bounds__(256) void gemm_kernel(
    const float* __restrict__ feat,
    const float* __restrict__ b,
    float4* __restrict__ out4)
{
    __shared__ float sW[IN_F * OUT_F];   // 32 KB, layout [k][o]
    __shared__ float sF[64 * IN_F];      // 32 KB, layout [n_local][k]

    const int tid = threadIdx.x;
    const int node0 = blockIdx.x * 64;

    // Zero the output (independent side-job): 800000 float4 over 782 blocks
    {
        const int per_blk = (N_NODES * OUT_F / 4 + gridDim.x - 1) / gridDim.x;
        int base = blockIdx.x * per_blk;
        for (int i = tid; i < per_blk; i += 256) {
            int idx = base + i;
            if (idx < N_NODES * OUT_F / 4)
                out4[idx] = make_float4(0.f, 0.f, 0.f, 0.f);
        }
    }

    // Load Wt ([k][o], contiguous) — coalesced, conflict-free STS
    {
        const float4* src = (const float4*)g_Wt;
        float4* dst = (float4*)sW;
        #pragma unroll
        for (int i = 0; i < 8; i++) dst[tid + i * 256] = src[tid + i * 256];
    }
    // Load 64 feat rows (float4), zero-pad past N_NODES
    {
        const float4* src = (const float4*)feat;
        float4* dst = (float4*)sF;
        #pragma unroll
        for (int i = 0; i < 8; i++) {
            int idx = tid + i * 256;         // float4 index in tile
            int n   = idx >> 5;              // 32 float4 per row
            int node = node0 + n;
            dst[idx] = (node < N_NODES) ? src[(size_t)node * 32 + (idx & 31)]
                                        : make_float4(0.f, 0.f, 0.f, 0.f);
        }
    }
    __syncthreads();

    const int og = tid & 15;    // outs og*4 .. og*4+3
    const int nl = tid >> 4;    // nodes nl, nl+16, nl+32, nl+48

    const float4 bv = ((const float4*)b)[og];
    float4 acc0 = bv, acc1 = bv, acc2 = bv, acc3 = bv;

    const float4* f0p = (const float4*)(sF + (nl     ) * IN_F);
    const float4* f1p = (const float4*)(sF + (nl + 16) * IN_F);
    const float4* f2p = (const float4*)(sF + (nl + 32) * IN_F);
    const float4* f3p = (const float4*)(sF + (nl + 48) * IN_F);
    const float4* w4  = (const float4*)sW;   // [k][16 groups]

    #pragma unroll
    for (int k4 = 0; k4 < IN_F / 4; k4++) {
        float4 f0 = f0p[k4], f1 = f1p[k4], f2 = f2p[k4], f3 = f3p[k4];
        #pragma unroll
        for (int j = 0; j < 4; j++) {
            const float4 w = w4[(k4 * 4 + j) * 16 + og];
            const float a = (&f0.x)[j], bb = (&f1.x)[j], c = (&f2.x)[j], d = (&f3.x)[j];
            acc0.x = fmaf(a, w.x, acc0.x); acc0.y = fmaf(a, w.y, acc0.y);
            acc0.z = fmaf(a, w.z, acc0.z); acc0.w = fmaf(a, w.w, acc0.w);
            acc1.x = fmaf(bb, w.x, acc1.x); acc1.y = fmaf(bb, w.y, acc1.y);
            acc1.z = fmaf(bb, w.z, acc1.z); acc1.w = fmaf(bb, w.w, acc1.w);
            acc2.x = fmaf(c, w.x, acc2.x); acc2.y = fmaf(c, w.y, acc2.y);
            acc2.z = fmaf(c, w.z, acc2.z); acc2.w = fmaf(c, w.w, acc2.w);
            acc3.x = fmaf(d, w.x, acc3.x); acc3.y = fmaf(d, w.y, acc3.y);
            acc3.z = fmaf(d, w.z, acc3.z); acc3.w = fmaf(d, w.w, acc3.w);
        }
    }

    #pragma unroll
    for (int i = 0; i < 4; i++) {
        const int node = node0 + nl + i * 16;
        if (node < N_NODES) {
            float4 v = (i == 0) ? acc0 : (i == 1) ? acc1 : (i == 2) ? acc2 : acc3;
            *(float4*)(g_h + (size_t)node * OUT_F + og * 4) = v;
        }
    }
}

// ---------------------------------------------------------------------------
// Scatter: out[dst] += h[src] * w.
// One edge per HALF-warp; lane16 owns float4 chunk lane16*4 of the 64-wide row.
// red.global.add.v4.f32: 16 REDG ops/edge.
// ---------------------------------------------------------------------------
__device__ __forceinline__ void red_add_v4(float* ptr, float4 v) {
    asm volatile("red.global.add.v4.f32 [%0], {%1, %2, %3, %4};"
                 :: "l"(ptr), "f"(v.x), "f"(v.y), "f"(v.z), "f"(v.w)
                 : "memory");
}

__global__ __launch_bounds__(256) void scatter_kernel(
    const int* __restrict__ esrc,
    const int* __restrict__ edst,
    const float* __restrict__ ew,
    float* __restrict__ out)
{
    const int half_id = threadIdx.x >> 4;         // 0..15 within block
    const int lane16  = threadIdx.x & 15;
    const int e = blockIdx.x * 16 + half_id;      // 16 edges per block
    if (e >= N_EDGES) return;

    const int   s = esrc[e];    // broadcast within half-warp
    const int   d = edst[e];
    const float w = ew[e];

    float4 hv = *(const float4*)(g_h + (size_t)s * OUT_F + lane16 * 4);
    hv.x *= w; hv.y *= w; hv.z *= w; hv.w *= w;
    red_add_v4(out + (size_t)d * OUT_F + lane16 * 4, hv);
}

// ---------------------------------------------------------------------------
extern "C" void kernel_launch(void* const* d_in, const int* in_sizes, int n_in,
                              void* d_out, int out_size) {
    const float* feat = (const float*)d_in[0];
    const int*   esrc = (const int*)d_in[1];   // int32 (JAX x64 disabled)
    const int*   edst = (const int*)d_in[2];
    const float* ew   = (const float*)d_in[3];
    const float* W    = (const float*)d_in[4];
    const float* b    = (const float*)d_in[5];
    float* out = (float*)d_out;

    prep_kernel<<<32, 256>>>(W);                              // transpose only

    gemm_kernel<<<(N_NODES + 63) / 64, 256>>>(feat, b, (float4*)out);

    scatter_kernel<<<N_EDGES / 16, 256>>>(esrc, edst, ew, out);
}

// round 5
// speedup vs baseline: 1.5505x; 1.0240x over previous
#include <cuda_runtime.h>
#include <cuda_fp16.h>
#include <stdint.h>

#define N_NODES 50000
#define N_EDGES 800000
#define IN_F    128
#define OUT_F   64

// Scratch (allocation-free rule: __device__ globals)
__device__ __half g_h[(size_t)N_NODES * OUT_F];  // 6.4 MB, L2-resident (fp16!)
__device__ float  g_Wt[IN_F * OUT_F];            // W transposed: Wt[k][o]

// ---------------------------------------------------------------------------
// Prep: transpose W only (tiny).
// ---------------------------------------------------------------------------
__global__ __launch_bounds__(256) void prep_kernel(const float* __restrict__ W) {
    const int idx = blockIdx.x * 256 + threadIdx.x;
    if (idx < IN_F * OUT_F) {
        int o = idx >> 7;      // /128
        int k = idx & 127;
        g_Wt[k * OUT_F + o] = W[idx];
    }
}

// ---------------------------------------------------------------------------
// GEMM: h = feat @ W^T + b   (fp32 compute, fp16 store)
// Tile: 64 nodes x 64 outs per block (256 threads), 4 nodes x 4 outs/thread.
// Also zeroes `out` (hidden behind compute).
// ---------------------------------------------------------------------------
__global__ __launch_bounds__(256) void gemm_kernel(
    const float* __restrict__ feat,
    const float* __restrict__ b,
    float4* __restrict__ out4)
{
    __shared__ float sW[IN_F * OUT_F];   // 32 KB, layout [k][o]
    __shared__ float sF[64 * IN_F];      // 32 KB, layout [n_local][k]

    const int tid = threadIdx.x;
    const int node0 = blockIdx.x * 64;

    // Zero the output (independent side-job)
    {
        const int per_blk = (N_NODES * OUT_F / 4 + gridDim.x - 1) / gridDim.x;
        int base = blockIdx.x * per_blk;
        for (int i = tid; i < per_blk; i += 256) {
            int idx = base + i;
            if (idx < N_NODES * OUT_F / 4)
                out4[idx] = make_float4(0.f, 0.f, 0.f, 0.f);
        }
    }

    // Load Wt ([k][o], contiguous) — coalesced, conflict-free STS
    {
        const float4* src = (const float4*)g_Wt;
        float4* dst = (float4*)sW;
        #pragma unroll
        for (int i = 0; i < 8; i++) dst[tid + i * 256] = src[tid + i * 256];
    }
    // Load 64 feat rows (float4), zero-pad past N_NODES
    {
        const float4* src = (const float4*)feat;
        float4* dst = (float4*)sF;
        #pragma unroll
        for (int i = 0; i < 8; i++) {
            int idx = tid + i * 256;         // float4 index in tile
            int n   = idx >> 5;              // 32 float4 per row
            int node = node0 + n;
            dst[idx] = (node < N_NODES) ? src[(size_t)node * 32 + (idx & 31)]
                                        : make_float4(0.f, 0.f, 0.f, 0.f);
        }
    }
    __syncthreads();

    const int og = tid & 15;    // outs og*4 .. og*4+3
    const int nl = tid >> 4;    // nodes nl, nl+16, nl+32, nl+48

    const float4 bv = ((const float4*)b)[og];
    float4 acc0 = bv, acc1 = bv, acc2 = bv, acc3 = bv;

    const float4* f0p = (const float4*)(sF + (nl     ) * IN_F);
    const float4* f1p = (const float4*)(sF + (nl + 16) * IN_F);
    const float4* f2p = (const float4*)(sF + (nl + 32) * IN_F);
    const float4* f3p = (const float4*)(sF + (nl + 48) * IN_F);
    const float4* w4  = (const float4*)sW;   // [k][16 groups]

    #pragma unroll
    for (int k4 = 0; k4 < IN_F / 4; k4++) {
        float4 f0 = f0p[k4], f1 = f1p[k4], f2 = f2p[k4], f3 = f3p[k4];
        #pragma unroll
        for (int j = 0; j < 4; j++) {
            const float4 w = w4[(k4 * 4 + j) * 16 + og];
            const float a = (&f0.x)[j], bb = (&f1.x)[j], c = (&f2.x)[j], d = (&f3.x)[j];
            acc0.x = fmaf(a, w.x, acc0.x); acc0.y = fmaf(a, w.y, acc0.y);
            acc0.z = fmaf(a, w.z, acc0.z); acc0.w = fmaf(a, w.w, acc0.w);
            acc1.x = fmaf(bb, w.x, acc1.x); acc1.y = fmaf(bb, w.y, acc1.y);
            acc1.z = fmaf(bb, w.z, acc1.z); acc1.w = fmaf(bb, w.w, acc1.w);
            acc2.x = fmaf(c, w.x, acc2.x); acc2.y = fmaf(c, w.y, acc2.y);
            acc2.z = fmaf(c, w.z, acc2.z); acc2.w = fmaf(c, w.w, acc2.w);
            acc3.x = fmaf(d, w.x, acc3.x); acc3.y = fmaf(d, w.y, acc3.y);
            acc3.z = fmaf(d, w.z, acc3.z); acc3.w = fmaf(d, w.w, acc3.w);
        }
    }

    #pragma unroll
    for (int i = 0; i < 4; i++) {
        const int node = node0 + nl + i * 16;
        if (node < N_NODES) {
            float4 v = (i == 0) ? acc0 : (i == 1) ? acc1 : (i == 2) ? acc2 : acc3;
            __half2 h0 = __floats2half2_rn(v.x, v.y);
            __half2 h1 = __floats2half2_rn(v.z, v.w);
            uint2 pk;
            pk.x = *(const unsigned int*)&h0;
            pk.y = *(const unsigned int*)&h1;
            *(uint2*)(g_h + (size_t)node * OUT_F + og * 4) = pk;
        }
    }
}

// ---------------------------------------------------------------------------
// Scatter: out[dst] += h[src] * w.
// One edge per HALF-warp; lane16 owns outs lane16*4..+3.
// Gather fp16 (8 B/lane -> 128 B/edge), accumulate fp32 via red.global.v4.f32.
// ---------------------------------------------------------------------------
__device__ __forceinline__ void red_add_v4(float* ptr, float4 v) {
    asm volatile("red.global.add.v4.f32 [%0], {%1, %2, %3, %4};"
                 :: "l"(ptr), "f"(v.x), "f"(v.y), "f"(v.z), "f"(v.w)
                 : "memory");
}

__global__ __launch_bounds__(256) void scatter_kernel(
    const int* __restrict__ esrc,
    const int* __restrict__ edst,
    const float* __restrict__ ew,
    float* __restrict__ out)
{
    const int half_id = threadIdx.x >> 4;         // 0..15 within block
    const int lane16  = threadIdx.x & 15;
    const int e = blockIdx.x * 16 + half_id;      // 16 edges per block
    if (e >= N_EDGES) return;

    const int   s = esrc[e];    // broadcast within half-warp
    const int   d = edst[e];
    const float w = ew[e];

    const uint2 hraw = *(const uint2*)(g_h + (size_t)s * OUT_F + lane16 * 4);
    const __half2 h0 = *(const __half2*)&hraw.x;
    const __half2 h1 = *(const __half2*)&hraw.y;
    const float2 f0 = __half22float2(h0);
    const float2 f1 = __half22float2(h1);

    float4 hv = make_float4(f0.x * w, f0.y * w, f1.x * w, f1.y * w);
    red_add_v4(out + (size_t)d * OUT_F + lane16 * 4, hv);
}

// ---------------------------------------------------------------------------
extern "C" void kernel_launch(void* const* d_in, const int* in_sizes, int n_in,
                              void* d_out, int out_size) {
    const float* feat = (const float*)d_in[0];
    const int*   esrc = (const int*)d_in[1];   // int32 (JAX x64 disabled)
    const int*   edst = (const int*)d_in[2];
    const float* ew   = (const float*)d_in[3];
    const float* W    = (const float*)d_in[4];
    const float* b    = (const float*)d_in[5];
    float* out = (float*)d_out;

    prep_kernel<<<32, 256>>>(W);                              // transpose only

    gemm_kernel<<<(N_NODES + 63) / 64, 256>>>(feat, b, (float4*)out);

    scatter_kernel<<<N_EDGES / 16, 256>>>(esrc, edst, ew, out);
}